// round 3
// baseline (speedup 1.0000x reference)
#include <cuda_runtime.h>
#include <math.h>
#include <float.h>

#define HID 128
#define MAX_N 20000
#define MAX_NC 5000
#define MAX_E 340000   /* E + n (self loops) */
#define NSPLIT 8
#define KNN_K 3
#define KNN_BLOCKS 296

/* ------------------------------ scratch ------------------------------ */
__device__ float g_lin [MAX_N * HID];
__device__ float g_hr1 [MAX_N * HID];
__device__ float g_hr  [MAX_N * HID];
__device__ float g_hc1 [MAX_NC * HID];
__device__ float g_hc  [MAX_NC * HID];
__device__ float g_es  [MAX_N];
__device__ float g_ed  [MAX_N];
__device__ int   g_deg [MAX_N];
__device__ int   g_rowptr[MAX_N + 1];
__device__ int   g_wp  [MAX_N];
__device__ int   g_csr_src[MAX_E];
__device__ float g_csr_e  [MAX_E];
__device__ float g_rnorm[MAX_N];
__device__ float g_pv [MAX_NC * NSPLIT * KNN_K];
__device__ int   g_pi [MAX_NC * NSPLIT * KNN_K];
__device__ int   g_nn [MAX_NC * KNN_K];
__device__ float g_pool[MAX_N * HID];
__device__ int   g_cnt [MAX_N];
__device__ int   g_work;

/* --------------------- h = x @ W ; e_src/e_dst dots ------------------- */
__global__ void linear_attn_kernel(const float* __restrict__ x,
                                   const float* __restrict__ W,
                                   const float* __restrict__ a_s,
                                   const float* __restrict__ a_d,
                                   float* __restrict__ h,
                                   float* __restrict__ es,
                                   float* __restrict__ ed,
                                   int n, int d_in) {
    int node = blockIdx.x;
    int f = threadIdx.x;
    __shared__ float xs[HID];
    __shared__ float r1[HID];
    __shared__ float r2[HID];
    if (f < d_in) xs[f] = x[node * d_in + f];
    __syncthreads();
    float acc = 0.f;
    for (int k = 0; k < d_in; k++) acc += xs[k] * W[k * HID + f];
    h[node * HID + f] = acc;
    r1[f] = acc * a_s[f];
    r2[f] = acc * a_d[f];
    __syncthreads();
    for (int s = 64; s > 0; s >>= 1) {
        if (f < s) { r1[f] += r1[f + s]; r2[f] += r2[f + s]; }
        __syncthreads();
    }
    if (f == 0) { es[node] = r1[0]; ed[node] = r2[0]; }
}

/* ------------------------------ CSR build ----------------------------- */
__global__ void deg_kernel(const int* __restrict__ ei, int E, int n, int* deg) {
    int i = blockIdx.x * blockDim.x + threadIdx.x;
    if (i >= E + n) return;
    int dst = (i < E) ? ei[E + i] : (i - E);
    atomicAdd(&deg[dst], 1);
}

__global__ void scan_kernel(const int* __restrict__ deg, int* rowptr, int* wp, int n) {
    __shared__ int sh[1024];
    __shared__ int soff;
    int tid = threadIdx.x;
    if (tid == 0) soff = 0;
    __syncthreads();
    for (int base = 0; base < n; base += 1024) {
        int i = base + tid;
        int v = (i < n) ? deg[i] : 0;
        sh[tid] = v;
        __syncthreads();
        for (int d = 1; d < 1024; d <<= 1) {
            int t = (tid >= d) ? sh[tid - d] : 0;
            __syncthreads();
            sh[tid] += t;
            __syncthreads();
        }
        int excl = soff + sh[tid] - v;
        if (i < n) { rowptr[i] = excl; wp[i] = excl; }
        __syncthreads();
        if (tid == 0) soff += sh[1023];
        __syncthreads();
    }
    if (tid == 0) rowptr[n] = soff;
}

__global__ void scatter_kernel(const int* __restrict__ ei, int E, int n,
                               const float* __restrict__ es,
                               const float* __restrict__ ed,
                               int* wp, int* csr_src, float* csr_e) {
    int i = blockIdx.x * blockDim.x + threadIdx.x;
    if (i >= E + n) return;
    int src, dst;
    if (i < E) { src = ei[i]; dst = ei[E + i]; }
    else       { src = i - E; dst = i - E; }
    int pos = atomicAdd(&wp[dst], 1);
    float e = es[src] + ed[dst];
    e = (e > 0.f) ? e : 0.2f * e;   /* leaky relu 0.2 */
    csr_src[pos] = src;
    csr_e[pos]   = e;
}

/* --------------- softmax over in-edges + weighted aggregation --------- */
__global__ void aggregate_kernel(const float* __restrict__ h,
                                 const float* __restrict__ bias,
                                 const int* __restrict__ rowptr,
                                 const int* __restrict__ csr_src,
                                 const float* __restrict__ csr_e,
                                 float* __restrict__ out, int n) {
    int node = (blockIdx.x * blockDim.x + threadIdx.x) >> 5;
    int lane = threadIdx.x & 31;
    if (node >= n) return;
    int b0 = rowptr[node], b1 = rowptr[node + 1];

    float m = -FLT_MAX;
    for (int j = b0 + lane; j < b1; j += 32) m = fmaxf(m, csr_e[j]);
    for (int o = 16; o > 0; o >>= 1) m = fmaxf(m, __shfl_down_sync(0xffffffffu, m, o));
    m = __shfl_sync(0xffffffffu, m, 0);

    float s = 0.f;
    for (int j = b0 + lane; j < b1; j += 32) s += __expf(csr_e[j] - m);
    for (int o = 16; o > 0; o >>= 1) s += __shfl_down_sync(0xffffffffu, s, o);
    s = __shfl_sync(0xffffffffu, s, 0);
    float inv = 1.f / fmaxf(s, 1e-16f);

    const float4* h4 = (const float4*)h;
    float4 acc = make_float4(0.f, 0.f, 0.f, 0.f);
    for (int j = b0; j < b1; j++) {
        float w = __expf(csr_e[j] - m) * inv;
        int src = csr_src[j];
        float4 hv = h4[src * 32 + lane];
        acc.x += w * hv.x; acc.y += w * hv.y;
        acc.z += w * hv.z; acc.w += w * hv.w;
    }
    float4 bb = ((const float4*)bias)[lane];
    acc.x = fmaxf(acc.x + bb.x, 0.f);
    acc.y = fmaxf(acc.y + bb.y, 0.f);
    acc.z = fmaxf(acc.z + bb.z, 0.f);
    acc.w = fmaxf(acc.w + bb.w, 0.f);
    ((float4*)out)[node * 32 + lane] = acc;
}

/* ------------------------------- KNN ---------------------------------- */
__global__ void rnorm_kernel(const float* __restrict__ h, float* __restrict__ rn, int n) {
    int w = (blockIdx.x * blockDim.x + threadIdx.x) >> 5;
    int lane = threadIdx.x & 31;
    if (w >= n) return;
    float4 v = ((const float4*)h)[w * 32 + lane];
    float s = v.x * v.x + v.y * v.y + v.z * v.z + v.w * v.w;
    for (int o = 16; o > 0; o >>= 1) s += __shfl_down_sync(0xffffffffu, s, o);
    if (lane == 0) rn[w] = s;
}

__device__ __forceinline__ void top3_insert(float v, int id, float tv[3], int ti[3]) {
    if (v < tv[2] || (v == tv[2] && id < ti[2])) {
        tv[2] = v; ti[2] = id;
        if (tv[2] < tv[1] || (tv[2] == tv[1] && ti[2] < ti[1])) {
            float fv = tv[1]; tv[1] = tv[2]; tv[2] = fv;
            int ii = ti[1]; ti[1] = ti[2]; ti[2] = ii;
        }
        if (tv[1] < tv[0] || (tv[1] == tv[0] && ti[1] < ti[0])) {
            float fv = tv[0]; tv[0] = tv[1]; tv[1] = fv;
            int ii = ti[0]; ti[0] = ti[1]; ti[1] = ii;
        }
    }
}

__device__ __forceinline__ unsigned long long bcast2(float x) {
    unsigned long long r;
    asm("mov.b64 %0, {%1, %1};" : "=l"(r) : "f"(x));
    return r;
}
__device__ __forceinline__ void ffma2(unsigned long long& d,
                                      unsigned long long a, unsigned long long b) {
    asm("fma.rn.f32x2 %0, %1, %2, %0;" : "+l"(d) : "l"(a), "l"(b));
}
__device__ __forceinline__ void unpack2(unsigned long long v, float& lo, float& hi) {
    asm("mov.b64 {%0, %1}, %2;" : "=f"(lo), "=f"(hi) : "l"(v));
}

/* Persistent-CTA KNN: work item = (c-tile of 64, resting split of ceil(n_r/NSPLIT)).
   Tiles stored TRANSPOSED in smem: As[k][c], Bs[k][r] so FFMA2 (f32x2) pairs
   adjacent colliders for free. Per thread: 4 colliders (2 reg-pairs) x 4 resting.
   Selection key s = |h_r|^2 - 2*dot (collider norm is row-constant). */
__global__ void __launch_bounds__(256, 2)
knn_kernel(const float* __restrict__ hc, const float* __restrict__ hr,
           const float* __restrict__ rn,
           int n_c, int n_r, int half, int n_items,
           float* __restrict__ pv, int* __restrict__ pi) {
    extern __shared__ float smem[];
    float* As   = smem;               /* [128][64] */
    float* Bs   = smem + 128 * 64;    /* [128][64] */
    float* rn_s = smem + 2 * 128 * 64;/* [64] */
    __shared__ int s_item;

    int t = threadIdx.x;
    int tx = t & 15, ty = t >> 4;
    int ty4 = ty * 4, tx4 = tx * 4;
    const float4* hc4 = (const float4*)hc;
    const float4* hr4 = (const float4*)hr;

    for (;;) {
        __syncthreads();
        if (t == 0) s_item = atomicAdd(&g_work, 1);
        __syncthreads();
        int item = s_item;
        if (item >= n_items) break;

        int ctile = item / NSPLIT;
        int split = item - ctile * NSPLIT;
        int cbase = ctile * 64;
        int rstart = split * half;
        int rmax = min(rstart + half, n_r);

        /* load collider tile transposed: As[k][c] */
#pragma unroll
        for (int m = 0; m < 8; m++) {
            int idx = t + m * 256;
            int c = idx & 63, k4 = idx >> 6;
            float4 v = make_float4(0.f, 0.f, 0.f, 0.f);
            if (cbase + c < n_c) v = hc4[(cbase + c) * 32 + k4];
            As[(k4 * 4 + 0) * 64 + c] = v.x;
            As[(k4 * 4 + 1) * 64 + c] = v.y;
            As[(k4 * 4 + 2) * 64 + c] = v.z;
            As[(k4 * 4 + 3) * 64 + c] = v.w;
        }

        float tv[4][3]; int ti[4][3];
#pragma unroll
        for (int i = 0; i < 4; i++)
#pragma unroll
            for (int s = 0; s < 3; s++) { tv[i][s] = FLT_MAX; ti[i][s] = 0x7fffffff; }

        int ntiles = (rmax - rstart + 63) >> 6;
        for (int tile = 0; tile < ntiles; tile++) {
            int rbase = rstart + tile * 64;
            __syncthreads();
            /* load resting tile transposed: Bs[k][r] */
#pragma unroll
            for (int m = 0; m < 8; m++) {
                int idx = t + m * 256;
                int r = idx & 63, k4 = idx >> 6;
                float4 v = make_float4(0.f, 0.f, 0.f, 0.f);
                if (rbase + r < rmax) v = hr4[(rbase + r) * 32 + k4];
                Bs[(k4 * 4 + 0) * 64 + r] = v.x;
                Bs[(k4 * 4 + 1) * 64 + r] = v.y;
                Bs[(k4 * 4 + 2) * 64 + r] = v.z;
                Bs[(k4 * 4 + 3) * 64 + r] = v.w;
            }
            if (t < 64) rn_s[t] = (rbase + t < rmax) ? rn[rbase + t] : 0.f;
            __syncthreads();

            unsigned long long acc[2][4];
#pragma unroll
            for (int p = 0; p < 2; p++)
#pragma unroll
                for (int j = 0; j < 4; j++) acc[p][j] = 0ull;

#pragma unroll 4
            for (int k = 0; k < HID; k++) {
                ulonglong2 av = *(const ulonglong2*)(As + k * 64 + ty4);
                float4 b = *(const float4*)(Bs + k * 64 + tx4);
                unsigned long long b0 = bcast2(b.x);
                unsigned long long b1 = bcast2(b.y);
                unsigned long long b2 = bcast2(b.z);
                unsigned long long b3 = bcast2(b.w);
                ffma2(acc[0][0], av.x, b0); ffma2(acc[1][0], av.y, b0);
                ffma2(acc[0][1], av.x, b1); ffma2(acc[1][1], av.y, b1);
                ffma2(acc[0][2], av.x, b2); ffma2(acc[1][2], av.y, b2);
                ffma2(acc[0][3], av.x, b3); ffma2(acc[1][3], av.y, b3);
            }

#pragma unroll
            for (int j = 0; j < 4; j++) {
                int r = rbase + tx4 + j;
                if (r < rmax) {
                    float rv = rn_s[tx4 + j];
#pragma unroll
                    for (int p = 0; p < 2; p++) {
                        float lo, hi;
                        unpack2(acc[p][j], lo, hi);
                        top3_insert(rv - 2.f * lo, r, tv[2 * p + 0], ti[2 * p + 0]);
                        top3_insert(rv - 2.f * hi, r, tv[2 * p + 1], ti[2 * p + 1]);
                    }
                }
            }
        }

        /* merge 16 partial top3 lists per collider row (reuse Bs region) */
        __syncthreads();
        float* cv = Bs;                       /* [64][16][3] = 12KB */
        int*   ci = (int*)(Bs + 64 * 16 * 3); /* 12KB */
#pragma unroll
        for (int i = 0; i < 4; i++) {
            int c = ty4 + i;
#pragma unroll
            for (int s = 0; s < 3; s++) {
                cv[(c * 16 + tx) * 3 + s] = tv[i][s];
                ci[(c * 16 + tx) * 3 + s] = ti[i][s];
            }
        }
        __syncthreads();
        if (t < 64) {
            int c = t;
            float bv[3] = {FLT_MAX, FLT_MAX, FLT_MAX};
            int   bi[3] = {0x7fffffff, 0x7fffffff, 0x7fffffff};
            for (int q = 0; q < 16; q++)
                for (int s = 0; s < 3; s++)
                    top3_insert(cv[(c * 16 + q) * 3 + s], ci[(c * 16 + q) * 3 + s], bv, bi);
            int col = cbase + c;
            if (col < n_c) {
                for (int s = 0; s < 3; s++) {
                    pv[(col * NSPLIT + split) * 3 + s] = bv[s];
                    pi[(col * NSPLIT + split) * 3 + s] = bi[s];
                }
            }
        }
    }
}

__global__ void knn_merge_kernel(const float* __restrict__ pv, const int* __restrict__ pi,
                                 int* __restrict__ nn, int n_c) {
    int c = blockIdx.x * blockDim.x + threadIdx.x;
    if (c >= n_c) return;
    float bv[3] = {FLT_MAX, FLT_MAX, FLT_MAX};
    int   bi[3] = {0x7fffffff, 0x7fffffff, 0x7fffffff};
    for (int sp = 0; sp < NSPLIT; sp++)
        for (int s = 0; s < 3; s++)
            top3_insert(pv[(c * NSPLIT + sp) * 3 + s], pi[(c * NSPLIT + sp) * 3 + s], bv, bi);
    for (int s = 0; s < 3; s++) nn[c * 3 + s] = bi[s];
}

/* ----------------------------- pooling -------------------------------- */
__global__ void assign_kernel(const float* __restrict__ hc, const int* __restrict__ nn,
                              float* __restrict__ pool, int* __restrict__ cnt, int n_c) {
    int g = blockIdx.x * blockDim.x + threadIdx.x;
    int w = g >> 5, lane = g & 31;
    if (w >= n_c * KNN_K) return;
    int c = w / KNN_K;
    int idx = nn[w];
    if (lane == 0) atomicAdd(&cnt[idx], 1);
    float4 hv = ((const float4*)hc)[c * 32 + lane];
    atomicAdd(&pool[idx * HID + lane * 4 + 0], hv.x);
    atomicAdd(&pool[idx * HID + lane * 4 + 1], hv.y);
    atomicAdd(&pool[idx * HID + lane * 4 + 2], hv.z);
    atomicAdd(&pool[idx * HID + lane * 4 + 3], hv.w);
}

/* ------------------------------ decoder ------------------------------- */
__global__ void decode_kernel(const float* __restrict__ hr, const float* __restrict__ pool,
                              const int* __restrict__ cnt,
                              const float* __restrict__ Wd, const float* __restrict__ bd,
                              float* __restrict__ out, int n) {
    int i = (blockIdx.x * blockDim.x + threadIdx.x) >> 5;
    int lane = threadIdx.x & 31;
    if (i >= n) return;
    float inv = 1.f / fmaxf((float)cnt[i], 1.f);
    float a0 = 0.f, a1 = 0.f, a2 = 0.f;
    for (int f = lane; f < HID; f += 32) {
        float v = hr[i * HID + f];
        a0 += v * Wd[f * 3 + 0];
        a1 += v * Wd[f * 3 + 1];
        a2 += v * Wd[f * 3 + 2];
        float p = pool[i * HID + f] * inv;
        a0 += p * Wd[(HID + f) * 3 + 0];
        a1 += p * Wd[(HID + f) * 3 + 1];
        a2 += p * Wd[(HID + f) * 3 + 2];
    }
    for (int o = 16; o > 0; o >>= 1) {
        a0 += __shfl_down_sync(0xffffffffu, a0, o);
        a1 += __shfl_down_sync(0xffffffffu, a1, o);
        a2 += __shfl_down_sync(0xffffffffu, a2, o);
    }
    if (lane == 0) {
        out[i * 3 + 0] = a0 + bd[0];
        out[i * 3 + 1] = a1 + bd[1];
        out[i * 3 + 2] = a2 + bd[2];
    }
}

/* ------------------------------- host --------------------------------- */
static void run_gat(const float* x, int d_in, const int* ei, int E, int n,
                    const float* W, const float* as_, const float* ad_, const float* b,
                    float* out,
                    float* lin, float* es, float* ed,
                    int* deg, int* rowptr, int* wp, int* csr_src, float* csr_e) {
    linear_attn_kernel<<<n, 128>>>(x, W, as_, ad_, lin, es, ed, n, d_in);
    cudaMemsetAsync(deg, 0, (size_t)n * sizeof(int));
    int tot = E + n;
    deg_kernel<<<(tot + 255) / 256, 256>>>(ei, E, n, deg);
    scan_kernel<<<1, 1024>>>(deg, rowptr, wp, n);
    scatter_kernel<<<(tot + 255) / 256, 256>>>(ei, E, n, es, ed, wp, csr_src, csr_e);
    aggregate_kernel<<<(n + 7) / 8, 256>>>(lin, b, rowptr, csr_src, csr_e, out, n);
}

extern "C" void kernel_launch(void* const* d_in, const int* in_sizes, int n_in,
                              void* d_out, int out_size) {
    const float* x_r  = (const float*)d_in[0];
    const float* x_c  = (const float*)d_in[1];
    const int*   ei_r = (const int*)d_in[2];
    const int*   ei_c = (const int*)d_in[3];
    /* d_in[4] = knn_k (fixed = 3) */
    const float* W_r1 = (const float*)d_in[5];
    const float* as_r1 = (const float*)d_in[6];
    const float* ad_r1 = (const float*)d_in[7];
    const float* b_r1  = (const float*)d_in[8];
    const float* W_r2 = (const float*)d_in[9];
    const float* as_r2 = (const float*)d_in[10];
    const float* ad_r2 = (const float*)d_in[11];
    const float* b_r2  = (const float*)d_in[12];
    const float* W_c1 = (const float*)d_in[13];
    const float* as_c1 = (const float*)d_in[14];
    const float* ad_c1 = (const float*)d_in[15];
    const float* b_c1  = (const float*)d_in[16];
    const float* W_c2 = (const float*)d_in[17];
    const float* as_c2 = (const float*)d_in[18];
    const float* ad_c2 = (const float*)d_in[19];
    const float* b_c2  = (const float*)d_in[20];
    const float* W_dec = (const float*)d_in[21];
    const float* b_dec = (const float*)d_in[22];
    float* out = (float*)d_out;

    int n_r = in_sizes[0] / 6;
    int n_c = in_sizes[1] / 6;
    int E_r = in_sizes[2] / 2;
    int E_c = in_sizes[3] / 2;

    float *lin, *hr1, *hr, *hc1, *hc, *es, *ed, *csr_e, *rnorm, *pv, *pool;
    int *deg, *rowptr, *wp, *csr_src, *pi, *nn, *cnt, *work;
    cudaGetSymbolAddress((void**)&lin, g_lin);
    cudaGetSymbolAddress((void**)&hr1, g_hr1);
    cudaGetSymbolAddress((void**)&hr,  g_hr);
    cudaGetSymbolAddress((void**)&hc1, g_hc1);
    cudaGetSymbolAddress((void**)&hc,  g_hc);
    cudaGetSymbolAddress((void**)&es,  g_es);
    cudaGetSymbolAddress((void**)&ed,  g_ed);
    cudaGetSymbolAddress((void**)&deg, g_deg);
    cudaGetSymbolAddress((void**)&rowptr, g_rowptr);
    cudaGetSymbolAddress((void**)&wp,  g_wp);
    cudaGetSymbolAddress((void**)&csr_src, g_csr_src);
    cudaGetSymbolAddress((void**)&csr_e,   g_csr_e);
    cudaGetSymbolAddress((void**)&rnorm, g_rnorm);
    cudaGetSymbolAddress((void**)&pv, g_pv);
    cudaGetSymbolAddress((void**)&pi, g_pi);
    cudaGetSymbolAddress((void**)&nn, g_nn);
    cudaGetSymbolAddress((void**)&pool, g_pool);
    cudaGetSymbolAddress((void**)&cnt, g_cnt);
    cudaGetSymbolAddress((void**)&work, g_work);

    /* resting branch */
    run_gat(x_r, 6,  ei_r, E_r, n_r, W_r1, as_r1, ad_r1, b_r1, hr1,
            lin, es, ed, deg, rowptr, wp, csr_src, csr_e);
    run_gat(hr1, HID, ei_r, E_r, n_r, W_r2, as_r2, ad_r2, b_r2, hr,
            lin, es, ed, deg, rowptr, wp, csr_src, csr_e);
    /* collider branch */
    run_gat(x_c, 6,  ei_c, E_c, n_c, W_c1, as_c1, ad_c1, b_c1, hc1,
            lin, es, ed, deg, rowptr, wp, csr_src, csr_e);
    run_gat(hc1, HID, ei_c, E_c, n_c, W_c2, as_c2, ad_c2, b_c2, hc,
            lin, es, ed, deg, rowptr, wp, csr_src, csr_e);

    /* KNN (persistent CTAs, transposed tiles, f32x2 FMA) */
    rnorm_kernel<<<(n_r * 32 + 255) / 256, 256>>>(hr, rnorm, n_r);
    int half = (n_r + NSPLIT - 1) / NSPLIT;
    int nct = (n_c + 63) / 64;
    int n_items = nct * NSPLIT;
    size_t knn_smem = (size_t)(2 * 128 * 64 + 64) * sizeof(float);
    cudaFuncSetAttribute(knn_kernel, cudaFuncAttributeMaxDynamicSharedMemorySize,
                         (int)knn_smem);
    cudaMemsetAsync(work, 0, sizeof(int));
    knn_kernel<<<KNN_BLOCKS, 256, knn_smem>>>(hc, hr, rnorm, n_c, n_r, half,
                                              n_items, pv, pi);
    knn_merge_kernel<<<(n_c + 255) / 256, 256>>>(pv, pi, nn, n_c);

    /* pooling */
    cudaMemsetAsync(pool, 0, (size_t)n_r * HID * sizeof(float));
    cudaMemsetAsync(cnt, 0, (size_t)n_r * sizeof(int));
    int n_assign = n_c * KNN_K;
    assign_kernel<<<(n_assign * 32 + 255) / 256, 256>>>(hc, nn, pool, cnt, n_c);

    /* decode */
    decode_kernel<<<(n_r * 32 + 255) / 256, 256>>>(hr, pool, cnt, W_dec, b_dec, out, n_r);
}

// round 5
// speedup vs baseline: 1.5207x; 1.5207x over previous
#include <cuda_runtime.h>
#include <cuda_fp16.h>
#include <mma.h>
#include <math.h>
#include <float.h>

using namespace nvcuda;

#define HID 128
#define MAX_N 20000
#define MAX_NC 5000
#define MAX_NC_PAD 5120
#define MAX_E 340000
#define KNN_K 3
#define RSPLIT 16
#define TOPP 8
#define KNN_BLOCKS 296
#define LDT 136   /* padded smem leading dim (halves): 272B rows, conflict-free */

__device__ float g_lin [MAX_N * HID];
__device__ float g_hr1 [MAX_N * HID];
__device__ float g_hr  [MAX_N * HID];
__device__ float g_hc1 [MAX_NC * HID];
__device__ float g_hc  [MAX_NC * HID];
__device__ float g_es  [MAX_N];
__device__ float g_ed  [MAX_N];
__device__ int   g_deg [MAX_N];
__device__ int   g_rowptr[MAX_N + 1];
__device__ int   g_wp  [MAX_N];
__device__ int   g_csr_src[MAX_E];
__device__ float g_csr_e  [MAX_E];
__device__ float g_rnorm[MAX_N];
__device__ __half g_hch[MAX_NC_PAD * HID];
__device__ __half g_hrh[MAX_N * HID];
__device__ float g_pv [256 * MAX_NC_PAD];
__device__ int   g_pi [256 * MAX_NC_PAD];
__device__ int   g_cand[MAX_NC * TOPP];
__device__ float g_sc  [MAX_NC * TOPP];
__device__ int   g_nn [MAX_NC * KNN_K];
__device__ float g_pool[MAX_N * HID];
__device__ int   g_cnt [MAX_N];
__device__ int   g_work;

/* ---------------- GAT pipeline ---------------- */
__global__ void linear_attn_kernel(const float* __restrict__ x, const float* __restrict__ W,
                                   const float* __restrict__ a_s, const float* __restrict__ a_d,
                                   float* __restrict__ h, float* __restrict__ es,
                                   float* __restrict__ ed, int n, int d_in) {
    int node = blockIdx.x, f = threadIdx.x;
    __shared__ float xs[HID], r1[HID], r2[HID];
    if (f < d_in) xs[f] = x[node * d_in + f];
    __syncthreads();
    float acc = 0.f;
    for (int k = 0; k < d_in; k++) acc += xs[k] * W[k * HID + f];
    h[node * HID + f] = acc;
    r1[f] = acc * a_s[f];
    r2[f] = acc * a_d[f];
    __syncthreads();
    for (int s = 64; s > 0; s >>= 1) {
        if (f < s) { r1[f] += r1[f + s]; r2[f] += r2[f + s]; }
        __syncthreads();
    }
    if (f == 0) { es[node] = r1[0]; ed[node] = r2[0]; }
}

__global__ void deg_kernel(const int* __restrict__ ei, int E, int n, int* deg) {
    int i = blockIdx.x * blockDim.x + threadIdx.x;
    if (i >= E + n) return;
    int dst = (i < E) ? ei[E + i] : (i - E);
    atomicAdd(&deg[dst], 1);
}

__global__ void scan_kernel(const int* __restrict__ deg, int* rowptr, int* wp, int n) {
    __shared__ int warpsums[32];
    __shared__ int soff;
    int tid = threadIdx.x, lane = tid & 31, w = tid >> 5;
    if (tid == 0) soff = 0;
    __syncthreads();
    for (int base = 0; base < n; base += 1024) {
        int i = base + tid;
        int v = (i < n) ? deg[i] : 0;
        int x = v;
        for (int o = 1; o < 32; o <<= 1) {
            int y = __shfl_up_sync(0xffffffffu, x, o);
            if (lane >= o) x += y;
        }
        if (lane == 31) warpsums[w] = x;
        __syncthreads();
        if (w == 0) {
            int s = warpsums[lane];
            for (int o = 1; o < 32; o <<= 1) {
                int y = __shfl_up_sync(0xffffffffu, s, o);
                if (lane >= o) s += y;
            }
            warpsums[lane] = s;
        }
        __syncthreads();
        int excl = soff + (w > 0 ? warpsums[w - 1] : 0) + x - v;
        if (i < n) { rowptr[i] = excl; wp[i] = excl; }
        __syncthreads();
        if (tid == 0) soff += warpsums[31];
        __syncthreads();
    }
    if (tid == 0) rowptr[n] = soff;
}

__global__ void scatter_kernel(const int* __restrict__ ei, int E, int n,
                               const float* __restrict__ es, const float* __restrict__ ed,
                               int* wp, int* csr_src, float* csr_e) {
    int i = blockIdx.x * blockDim.x + threadIdx.x;
    if (i >= E + n) return;
    int src, dst;
    if (i < E) { src = ei[i]; dst = ei[E + i]; }
    else       { src = i - E; dst = i - E; }
    int pos = atomicAdd(&wp[dst], 1);
    float e = es[src] + ed[dst];
    e = (e > 0.f) ? e : 0.2f * e;
    csr_src[pos] = src;
    csr_e[pos]   = e;
}

__global__ void aggregate_kernel(const float* __restrict__ h, const float* __restrict__ bias,
                                 const int* __restrict__ rowptr, const int* __restrict__ csr_src,
                                 const float* __restrict__ csr_e, float* __restrict__ out, int n) {
    int node = (blockIdx.x * blockDim.x + threadIdx.x) >> 5;
    int lane = threadIdx.x & 31;
    if (node >= n) return;
    int b0 = rowptr[node], b1 = rowptr[node + 1];
    float m = -FLT_MAX;
    for (int j = b0 + lane; j < b1; j += 32) m = fmaxf(m, csr_e[j]);
    for (int o = 16; o > 0; o >>= 1) m = fmaxf(m, __shfl_down_sync(0xffffffffu, m, o));
    m = __shfl_sync(0xffffffffu, m, 0);
    float s = 0.f;
    for (int j = b0 + lane; j < b1; j += 32) s += __expf(csr_e[j] - m);
    for (int o = 16; o > 0; o >>= 1) s += __shfl_down_sync(0xffffffffu, s, o);
    s = __shfl_sync(0xffffffffu, s, 0);
    float inv = 1.f / fmaxf(s, 1e-16f);
    const float4* h4 = (const float4*)h;
    float4 acc = make_float4(0.f, 0.f, 0.f, 0.f);
    for (int j = b0; j < b1; j++) {
        float w = __expf(csr_e[j] - m) * inv;
        float4 hv = h4[csr_src[j] * 32 + lane];
        acc.x += w * hv.x; acc.y += w * hv.y; acc.z += w * hv.z; acc.w += w * hv.w;
    }
    float4 bb = ((const float4*)bias)[lane];
    acc.x = fmaxf(acc.x + bb.x, 0.f); acc.y = fmaxf(acc.y + bb.y, 0.f);
    acc.z = fmaxf(acc.z + bb.z, 0.f); acc.w = fmaxf(acc.w + bb.w, 0.f);
    ((float4*)out)[node * 32 + lane] = acc;
}

/* ---------------- KNN ---------------- */
__global__ void rnorm_kernel(const float* __restrict__ h, float* __restrict__ rn, int n) {
    int w = (blockIdx.x * blockDim.x + threadIdx.x) >> 5;
    int lane = threadIdx.x & 31;
    if (w >= n) return;
    float4 v = ((const float4*)h)[w * 32 + lane];
    float s = v.x * v.x + v.y * v.y + v.z * v.z + v.w * v.w;
    for (int o = 16; o > 0; o >>= 1) s += __shfl_down_sync(0xffffffffu, s, o);
    if (lane == 0) rn[w] = s;
}

__global__ void to_half_kernel(const float* __restrict__ x, __half* __restrict__ y, int n) {
    int i = blockIdx.x * blockDim.x + threadIdx.x;
    if (i < n) y[i] = __float2half_rn(x[i]);
}

__device__ __forceinline__ bool bet(float v, int id, float v2, int id2) {
    return v < v2 || (v == v2 && id < id2);
}
__device__ __forceinline__ void top3_insert(float v, int id, float tv[3], int ti[3]) {
    if (!bet(v, id, tv[2], ti[2])) return;
    tv[2] = v; ti[2] = id;
    if (bet(tv[2], ti[2], tv[1], ti[1])) {
        float f = tv[1]; tv[1] = tv[2]; tv[2] = f;
        int q = ti[1]; ti[1] = ti[2]; ti[2] = q;
    }
    if (bet(tv[1], ti[1], tv[0], ti[0])) {
        float f = tv[0]; tv[0] = tv[1]; tv[1] = f;
        int q = ti[0]; ti[0] = ti[1]; ti[1] = q;
    }
}
#define T8SW(a, b) \
    if (bet(tv[b], ti[b], tv[a], ti[a])) { \
        float f_ = tv[a]; tv[a] = tv[b]; tv[b] = f_; \
        int q_ = ti[a]; ti[a] = ti[b]; ti[b] = q_; }
__device__ __forceinline__ void top8_insert(float s, int id, float tv[8], int ti[8]) {
    if (!bet(s, id, tv[7], ti[7])) return;
    tv[7] = s; ti[7] = id;
    T8SW(6, 7) T8SW(5, 6) T8SW(4, 5) T8SW(3, 4) T8SW(2, 3) T8SW(1, 2) T8SW(0, 1)
}

/* Persistent wmma KNN. Item = (ctile of 128, rsplit of tiles_per r-tiles).
   Warp w owns c-rows [cbase+16w, +16). Lane: c-row = lane&15, col-half = lane>>4.
   dot = hc_fp16 . hr_fp16 via wmma f16->f32; s_hat = rn[r] - 2*dot.
   One running top-8 per lane -> 32 partial lists / collider / rsplit. */
__global__ void __launch_bounds__(256, 2)
knn_wmma_kernel(const __half* __restrict__ hch, const __half* __restrict__ hrh,
                const float* __restrict__ rn,
                int n_c, int n_r, int n_rtiles, int tiles_per, int n_items,
                float* __restrict__ pv, int* __restrict__ pi) {
    extern __shared__ char dsm[];
    __half* As = (__half*)dsm;                       /* [128][LDT] */
    __half* Bs = As + 128 * LDT;                     /* [128][LDT] */
    float*  scr = (float*)(Bs + 128 * LDT);          /* [8][256] per-warp */
    float*  rn_s = scr + 8 * 256;                    /* [128] */
    __shared__ int s_item;

    int tid = threadIdx.x, wid = tid >> 5, lane = tid & 31;
    int crow = lane & 15, chalf = lane >> 4;
    float* myscr = scr + wid * 256;

    for (;;) {
        __syncthreads();
        if (tid == 0) s_item = atomicAdd(&g_work, 1);
        __syncthreads();
        int item = s_item;
        if (item >= n_items) break;
        int ct = item / RSPLIT;
        int rs = item - ct * RSPLIT;
        int cbase = ct * 128;
        int t0 = rs * tiles_per;
        int t1 = min(t0 + tiles_per, n_rtiles);
        int my_c = cbase + wid * 16 + crow;

        /* load A tile: 128 colliders x 128 k fp16, rows padded to LDT */
#pragma unroll
        for (int m = 0; m < 8; m++) {
            int idx = tid + m * 256;
            int row = idx >> 4, k8 = idx & 15;
            int c = cbase + row;
            uint4 v = make_uint4(0, 0, 0, 0);
            if (c < n_c) v = ((const uint4*)hch)[c * 16 + k8];
            *(uint4*)&As[row * LDT + k8 * 8] = v;
        }

        float tv[8]; int ti[8];
#pragma unroll
        for (int s = 0; s < 8; s++) { tv[s] = FLT_MAX; ti[s] = 0x7fffffff; }

        for (int tt = t0; tt < t1; tt++) {
            int rbase = tt * 128;
            __syncthreads();
#pragma unroll
            for (int m = 0; m < 8; m++) {
                int idx = tid + m * 256;
                int row = idx >> 4, k8 = idx & 15;
                int r = rbase + row;
                uint4 v = make_uint4(0, 0, 0, 0);
                if (r < n_r) v = ((const uint4*)hrh)[r * 16 + k8];
                *(uint4*)&Bs[row * LDT + k8 * 8] = v;
            }
            if (tid < 128) {
                int r = rbase + tid;
                rn_s[tid] = (r < n_r) ? rn[r] : 1e30f;
            }
            __syncthreads();

            wmma::fragment<wmma::accumulator, 16, 16, 16, float> acc[8];
#pragma unroll
            for (int f = 0; f < 8; f++) wmma::fill_fragment(acc[f], 0.f);

#pragma unroll
            for (int k = 0; k < 8; k++) {
                wmma::fragment<wmma::matrix_a, 16, 16, 16, __half, wmma::row_major> af;
                wmma::load_matrix_sync(af, &As[(wid * 16) * LDT + k * 16], LDT);
#pragma unroll
                for (int f = 0; f < 8; f++) {
                    wmma::fragment<wmma::matrix_b, 16, 16, 16, __half, wmma::col_major> bf;
                    wmma::load_matrix_sync(bf, &Bs[(f * 16) * LDT + k * 16], LDT);
                    wmma::mma_sync(acc[f], af, bf, acc[f]);
                }
            }

            /* epilogue: stage each 16x16 D frag, scan (c-row, col-half) slice */
#pragma unroll
            for (int f = 0; f < 8; f++) {
                wmma::store_matrix_sync(myscr, acc[f], 16, wmma::mem_row_major);
                __syncwarp();
                int cb = f * 16 + chalf * 8;
#pragma unroll
                for (int j = 0; j < 8; j++) {
                    float d = myscr[crow * 16 + chalf * 8 + j];
                    float s = fmaf(-2.f, d, rn_s[cb + j]);
                    top8_insert(s, rbase + cb + j, tv, ti);
                }
                __syncwarp();
            }
        }

        if (my_c < n_c) {
            int ebase = (rs * 2 + chalf) * 8;
#pragma unroll
            for (int s = 0; s < 8; s++) {
                pv[(ebase + s) * MAX_NC_PAD + my_c] = tv[s];
                pi[(ebase + s) * MAX_NC_PAD + my_c] = ti[s];
            }
        }
    }
}

__global__ void merge8_kernel(const float* __restrict__ pv, const int* __restrict__ pi,
                              int n_c, int n_r, int* __restrict__ cand) {
    int c = blockIdx.x * blockDim.x + threadIdx.x;
    if (c >= n_c) return;
    float tv[8]; int ti[8];
#pragma unroll
    for (int s = 0; s < 8; s++) { tv[s] = FLT_MAX; ti[s] = 0x7fffffff; }
    for (int e = 0; e < 256; e++) {
        int id = pi[e * MAX_NC_PAD + c];
        if ((unsigned)id < (unsigned)n_r)
            top8_insert(pv[e * MAX_NC_PAD + c], id, tv, ti);
    }
#pragma unroll
    for (int j = 0; j < 8; j++) cand[c * TOPP + j] = ti[j];
}

__global__ void rescore_kernel(const int* __restrict__ cand, const float* __restrict__ hc,
                               const float* __restrict__ hr, const float* __restrict__ rn,
                               int n_c, int n_r, float* __restrict__ sc) {
    int gw = (blockIdx.x * blockDim.x + threadIdx.x) >> 5;
    int lane = threadIdx.x & 31;
    if (gw >= n_c * TOPP) return;
    int c = gw / TOPP, j = gw - c * TOPP;
    int id = cand[c * TOPP + j];
    float s = FLT_MAX;
    if ((unsigned)id < (unsigned)n_r) {
        float4 a = ((const float4*)hc)[c * 32 + lane];
        float4 b = ((const float4*)hr)[id * 32 + lane];
        float d = a.x * b.x + a.y * b.y + a.z * b.z + a.w * b.w;
        for (int o = 16; o > 0; o >>= 1) d += __shfl_down_sync(0xffffffffu, d, o);
        s = rn[id] - 2.f * d;
    }
    if (lane == 0) sc[c * TOPP + j] = s;
}

__global__ void final3_kernel(const float* __restrict__ sc, const int* __restrict__ cand,
                              int n_c, int n_r, int* __restrict__ nn) {
    int c = blockIdx.x * blockDim.x + threadIdx.x;
    if (c >= n_c) return;
    float bv[3] = {FLT_MAX, FLT_MAX, FLT_MAX};
    int   bi[3] = {0x7fffffff, 0x7fffffff, 0x7fffffff};
#pragma unroll
    for (int j = 0; j < TOPP; j++) {
        int id = cand[c * TOPP + j];
        if ((unsigned)id < (unsigned)n_r)
            top3_insert(sc[c * TOPP + j], id, bv, bi);
    }
    nn[c * 3 + 0] = bi[0]; nn[c * 3 + 1] = bi[1]; nn[c * 3 + 2] = bi[2];
}

/* ---------------- pooling + decode ---------------- */
__global__ void assign_kernel(const float* __restrict__ hc, const int* __restrict__ nn,
                              float* __restrict__ pool, int* __restrict__ cnt, int n_c) {
    int g = blockIdx.x * blockDim.x + threadIdx.x;
    int w = g >> 5, lane = g & 31;
    if (w >= n_c * KNN_K) return;
    int c = w / KNN_K;
    int idx = nn[w];
    if (lane == 0) atomicAdd(&cnt[idx], 1);
    float4 hv = ((const float4*)hc)[c * 32 + lane];
    atomicAdd(&pool[idx * HID + lane * 4 + 0], hv.x);
    atomicAdd(&pool[idx * HID + lane * 4 + 1], hv.y);
    atomicAdd(&pool[idx * HID + lane * 4 + 2], hv.z);
    atomicAdd(&pool[idx * HID + lane * 4 + 3], hv.w);
}

__global__ void decode_kernel(const float* __restrict__ hr, const float* __restrict__ pool,
                              const int* __restrict__ cnt, const float* __restrict__ Wd,
                              const float* __restrict__ bd, float* __restrict__ out, int n) {
    int i = (blockIdx.x * blockDim.x + threadIdx.x) >> 5;
    int lane = threadIdx.x & 31;
    if (i >= n) return;
    float inv = 1.f / fmaxf((float)cnt[i], 1.f);
    float a0 = 0.f, a1 = 0.f, a2 = 0.f;
    for (int f = lane; f < HID; f += 32) {
        float v = hr[i * HID + f];
        a0 += v * Wd[f * 3 + 0]; a1 += v * Wd[f * 3 + 1]; a2 += v * Wd[f * 3 + 2];
        float p = pool[i * HID + f] * inv;
        a0 += p * Wd[(HID + f) * 3 + 0]; a1 += p * Wd[(HID + f) * 3 + 1]; a2 += p * Wd[(HID + f) * 3 + 2];
    }
    for (int o = 16; o > 0; o >>= 1) {
        a0 += __shfl_down_sync(0xffffffffu, a0, o);
        a1 += __shfl_down_sync(0xffffffffu, a1, o);
        a2 += __shfl_down_sync(0xffffffffu, a2, o);
    }
    if (lane == 0) {
        out[i * 3 + 0] = a0 + bd[0];
        out[i * 3 + 1] = a1 + bd[1];
        out[i * 3 + 2] = a2 + bd[2];
    }
}

/* ---------------- host ---------------- */
static void run_gat(const float* x, int d_in, const int* ei, int E, int n,
                    const float* W, const float* as_, const float* ad_, const float* b,
                    float* out, float* lin, float* es, float* ed,
                    int* deg, int* rowptr, int* wp, int* csr_src, float* csr_e) {
    linear_attn_kernel<<<n, 128>>>(x, W, as_, ad_, lin, es, ed, n, d_in);
    cudaMemsetAsync(deg, 0, (size_t)n * sizeof(int));
    int tot = E + n;
    deg_kernel<<<(tot + 255) / 256, 256>>>(ei, E, n, deg);
    scan_kernel<<<1, 1024>>>(deg, rowptr, wp, n);
    scatter_kernel<<<(tot + 255) / 256, 256>>>(ei, E, n, es, ed, wp, csr_src, csr_e);
    aggregate_kernel<<<(n + 7) / 8, 256>>>(lin, b, rowptr, csr_src, csr_e, out, n);
}

extern "C" void kernel_launch(void* const* d_in, const int* in_sizes, int n_in,
                              void* d_out, int out_size) {
    const float* x_r  = (const float*)d_in[0];
    const float* x_c  = (const float*)d_in[1];
    const int*   ei_r = (const int*)d_in[2];
    const int*   ei_c = (const int*)d_in[3];
    const float* W_r1 = (const float*)d_in[5];
    const float* as_r1 = (const float*)d_in[6];
    const float* ad_r1 = (const float*)d_in[7];
    const float* b_r1  = (const float*)d_in[8];
    const float* W_r2 = (const float*)d_in[9];
    const float* as_r2 = (const float*)d_in[10];
    const float* ad_r2 = (const float*)d_in[11];
    const float* b_r2  = (const float*)d_in[12];
    const float* W_c1 = (const float*)d_in[13];
    const float* as_c1 = (const float*)d_in[14];
    const float* ad_c1 = (const float*)d_in[15];
    const float* b_c1  = (const float*)d_in[16];
    const float* W_c2 = (const float*)d_in[17];
    const float* as_c2 = (const float*)d_in[18];
    const float* ad_c2 = (const float*)d_in[19];
    const float* b_c2  = (const float*)d_in[20];
    const float* W_dec = (const float*)d_in[21];
    const float* b_dec = (const float*)d_in[22];
    float* out = (float*)d_out;

    int n_r = in_sizes[0] / 6;
    int n_c = in_sizes[1] / 6;
    int E_r = in_sizes[2] / 2;
    int E_c = in_sizes[3] / 2;

    float *lin, *hr1, *hr, *hc1, *hc, *es, *ed, *csr_e, *rnorm, *pv, *pool, *sc;
    __half *hch, *hrh;
    int *deg, *rowptr, *wp, *csr_src, *pi, *nn, *cnt, *work, *cand;
    cudaGetSymbolAddress((void**)&lin, g_lin);
    cudaGetSymbolAddress((void**)&hr1, g_hr1);
    cudaGetSymbolAddress((void**)&hr,  g_hr);
    cudaGetSymbolAddress((void**)&hc1, g_hc1);
    cudaGetSymbolAddress((void**)&hc,  g_hc);
    cudaGetSymbolAddress((void**)&es,  g_es);
    cudaGetSymbolAddress((void**)&ed,  g_ed);
    cudaGetSymbolAddress((void**)&deg, g_deg);
    cudaGetSymbolAddress((void**)&rowptr, g_rowptr);
    cudaGetSymbolAddress((void**)&wp,  g_wp);
    cudaGetSymbolAddress((void**)&csr_src, g_csr_src);
    cudaGetSymbolAddress((void**)&csr_e,   g_csr_e);
    cudaGetSymbolAddress((void**)&rnorm, g_rnorm);
    cudaGetSymbolAddress((void**)&hch, g_hch);
    cudaGetSymbolAddress((void**)&hrh, g_hrh);
    cudaGetSymbolAddress((void**)&pv, g_pv);
    cudaGetSymbolAddress((void**)&pi, g_pi);
    cudaGetSymbolAddress((void**)&cand, g_cand);
    cudaGetSymbolAddress((void**)&sc, g_sc);
    cudaGetSymbolAddress((void**)&nn, g_nn);
    cudaGetSymbolAddress((void**)&pool, g_pool);
    cudaGetSymbolAddress((void**)&cnt, g_cnt);
    cudaGetSymbolAddress((void**)&work, g_work);

    run_gat(x_r, 6,  ei_r, E_r, n_r, W_r1, as_r1, ad_r1, b_r1, hr1,
            lin, es, ed, deg, rowptr, wp, csr_src, csr_e);
    run_gat(hr1, HID, ei_r, E_r, n_r, W_r2, as_r2, ad_r2, b_r2, hr,
            lin, es, ed, deg, rowptr, wp, csr_src, csr_e);
    run_gat(x_c, 6,  ei_c, E_c, n_c, W_c1, as_c1, ad_c1, b_c1, hc1,
            lin, es, ed, deg, rowptr, wp, csr_src, csr_e);
    run_gat(hc1, HID, ei_c, E_c, n_c, W_c2, as_c2, ad_c2, b_c2, hc,
            lin, es, ed, deg, rowptr, wp, csr_src, csr_e);

    /* KNN: fp16 wmma candidate pass + exact fp32 rescore */
    rnorm_kernel<<<(n_r * 32 + 255) / 256, 256>>>(hr, rnorm, n_r);
    to_half_kernel<<<(n_c * HID + 255) / 256, 256>>>(hc, hch, n_c * HID);
    to_half_kernel<<<(n_r * HID + 255) / 256, 256>>>(hr, hrh, n_r * HID);

    int n_rtiles = (n_r + 127) / 128;
    int tiles_per = (n_rtiles + RSPLIT - 1) / RSPLIT;
    int nct = (n_c + 127) / 128;
    int n_items = nct * RSPLIT;
    size_t knn_smem = (size_t)(2 * 128 * LDT) * sizeof(__half)
                    + (size_t)(8 * 256 + 128) * sizeof(float);
    cudaFuncSetAttribute(knn_wmma_kernel, cudaFuncAttributeMaxDynamicSharedMemorySize,
                         (int)knn_smem);
    cudaMemsetAsync(work, 0, sizeof(int));
    knn_wmma_kernel<<<KNN_BLOCKS, 256, knn_smem>>>(hch, hrh, rnorm, n_c, n_r,
                                                   n_rtiles, tiles_per, n_items, pv, pi);
    merge8_kernel<<<(n_c + 127) / 128, 128>>>(pv, pi, n_c, n_r, cand);
    rescore_kernel<<<(n_c * TOPP * 32 + 255) / 256, 256>>>(cand, hc, hr, rnorm, n_c, n_r, sc);
    final3_kernel<<<(n_c + 255) / 256, 256>>>(sc, cand, n_c, n_r, nn);

    /* pooling */
    cudaMemsetAsync(pool, 0, (size_t)n_r * HID * sizeof(float));
    cudaMemsetAsync(cnt, 0, (size_t)n_r * sizeof(int));
    assign_kernel<<<(n_c * KNN_K * 32 + 255) / 256, 256>>>(hc, nn, pool, cnt, n_c);

    /* decode */
    decode_kernel<<<(n_r * 32 + 255) / 256, 256>>>(hr, pool, cnt, W_dec, b_dec, out, n_r);
}